// round 13
// baseline (speedup 1.0000x reference)
#include <cuda_runtime.h>
#include <cuda_bf16.h>
#include <cuda_fp16.h>
#include <math.h>
#include <stdint.h>

#define B_  8
#define T_  512
#define F_  1024
#define G4  4096           // 4*F
#define V_  32000
#define M_  (B_*T_)        // 4096 rows
#define K_  1024
#define LSTM_CTAS 128
#define TRANS_CTAS 20      // extra CTAs in lstm_persist that transpose Wd

// ---------------- scratch (device globals; no allocation allowed) ----------
__device__ float g_xW[(size_t)M_ * G4];              // 64 MB : x@Wx + b
__device__ float g_WhT[(size_t)G4 * F_];             // 16 MB : Wh^T [4F][F]
__device__ float g_h[2][B_ * F_];                    // ping-pong hidden state
__device__ unsigned g_bar;                           // grid barrier counter
__device__ unsigned g_rel;                           // grid barrier release flag
// bf16 split operands (input GEMM: exact to 2^-16, feeds recurrence)
__device__ __nv_bfloat16 g_Ahi[(size_t)M_ * K_];     // 8 MB : embed rows hi
__device__ __nv_bfloat16 g_Alo[(size_t)M_ * K_];     // 8 MB : embed rows lo
__device__ __nv_bfloat16 g_WxT_hi[(size_t)G4 * K_];  // 8 MB  [4F][F]
__device__ __nv_bfloat16 g_WxT_lo[(size_t)G4 * K_];  // 8 MB
// fp16 operands (projection GEMM: single product, calibrated err ~3e-4)
__device__ __half g_Ah[(size_t)M_ * K_];             // 8 MB : hs fp16
__device__ __half g_WdT[(size_t)V_ * K_];            // 64 MB [V][F] fp16

// ======================= PTX helpers (sm_103-safe) ==========================
__device__ __forceinline__ uint32_t smem_u32(const void* p) {
    uint32_t a;
    asm("{ .reg .u64 t; cvta.to.shared.u64 t, %1; cvt.u32.u64 %0, t; }"
        : "=r"(a) : "l"(p));
    return a;
}
__device__ __forceinline__ void cp16(uint32_t s, const void* g) {
    asm volatile("cp.async.cg.shared.global [%0], [%1], 16;"
                 :: "r"(s), "l"(g) : "memory");
}
#define CP_COMMIT() asm volatile("cp.async.commit_group;" ::: "memory")
#define CP_WAIT(n)  asm volatile("cp.async.wait_group %0;" :: "n"(n) : "memory")

__device__ __forceinline__ void ldsm4(uint32_t* r, uint32_t addr) {
    asm volatile("ldmatrix.sync.aligned.m8n8.x4.shared.b16 {%0,%1,%2,%3}, [%4];"
                 : "=r"(r[0]), "=r"(r[1]), "=r"(r[2]), "=r"(r[3]) : "r"(addr));
}
__device__ __forceinline__ void mma_bf16(float* c, const uint32_t* a,
                                         const uint32_t* b) {
    asm volatile(
        "mma.sync.aligned.m16n8k16.row.col.f32.bf16.bf16.f32 "
        "{%0,%1,%2,%3}, {%4,%5,%6,%7}, {%8,%9}, {%0,%1,%2,%3};"
        : "+f"(c[0]), "+f"(c[1]), "+f"(c[2]), "+f"(c[3])
        : "r"(a[0]), "r"(a[1]), "r"(a[2]), "r"(a[3]), "r"(b[0]), "r"(b[1]));
}
__device__ __forceinline__ void mma_f16(float* c, const uint32_t* a,
                                        const uint32_t* b) {
    asm volatile(
        "mma.sync.aligned.m16n8k16.row.col.f32.f16.f16.f32 "
        "{%0,%1,%2,%3}, {%4,%5,%6,%7}, {%8,%9}, {%0,%1,%2,%3};"
        : "+f"(c[0]), "+f"(c[1]), "+f"(c[2]), "+f"(c[3])
        : "r"(a[0]), "r"(a[1]), "r"(a[2]), "r"(a[3]), "r"(b[0]), "r"(b[1]));
}
// packed fp32x2 FMA (sm_100+ family, not 'a'-gated)
__device__ __forceinline__ uint64_t fma2(uint64_t a, uint64_t b, uint64_t c) {
    uint64_t d;
    asm("fma.rn.f32x2 %0, %1, %2, %3;" : "=l"(d) : "l"(a), "l"(b), "l"(c));
    return d;
}
__device__ __forceinline__ float unpack_add(uint64_t a) {
    float lo, hi;
    asm("mov.b64 {%0,%1}, %2;" : "=f"(lo), "=f"(hi) : "l"(a));
    return lo + hi;
}

// ======================= prep kernels =======================================
__global__ void init_state() {
    int i = blockIdx.x * blockDim.x + threadIdx.x;
    if (i < B_ * F_) { g_h[0][i] = 0.f; g_h[1][i] = 0.f; }
    if (i == 0) { g_bar = 0u; g_rel = 0u; }
}

__global__ void transpose_wh(const float* __restrict__ Wh) {
    __shared__ float tile[32][33];
    int n = blockIdx.x * 32 + threadIdx.x;
    int k = blockIdx.y * 32 + threadIdx.y;
    tile[threadIdx.y][threadIdx.x] = Wh[(size_t)k * G4 + n];
    __syncthreads();
    int n2 = blockIdx.x * 32 + threadIdx.y;
    int k2 = blockIdx.y * 32 + threadIdx.x;
    g_WhT[(size_t)n2 * F_ + k2] = tile[threadIdx.x][threadIdx.y];
}

// embed[tokens] fp32 -> hi/lo bf16 rows
__global__ void split_rows(const float* __restrict__ src,
                           const int* __restrict__ tokens,
                           __nv_bfloat16* __restrict__ hi,
                           __nv_bfloat16* __restrict__ lo) {
    size_t idx = (size_t)blockIdx.x * blockDim.x + threadIdx.x;
    if (idx >= (size_t)M_ * K_) return;
    size_t row = idx >> 10, col = idx & 1023;
    float x = src[(size_t)tokens[row] * K_ + col];
    __nv_bfloat16 h = __float2bfloat16(x);
    hi[idx] = h;
    lo[idx] = __float2bfloat16(x - __bfloat162float(h));
}

// W fp32 [1024 x N] -> WT hi/lo bf16 [N x 1024]   (Wx path)
__global__ void transpose_split(const float* __restrict__ W,
                                __nv_bfloat16* __restrict__ Thi,
                                __nv_bfloat16* __restrict__ Tlo, int N) {
    __shared__ float tile[32][33];
    int n  = blockIdx.x * 32 + threadIdx.x;
    int k0 = blockIdx.y * 32;
#pragma unroll
    for (int r = threadIdx.y; r < 32; r += 8)
        tile[r][threadIdx.x] = W[(size_t)(k0 + r) * N + n];
    __syncthreads();
#pragma unroll
    for (int rr = threadIdx.y; rr < 32; rr += 8) {
        int n2 = blockIdx.x * 32 + rr;
        int k2 = k0 + threadIdx.x;
        float x = tile[threadIdx.x][rr];
        __nv_bfloat16 h = __float2bfloat16(x);
        size_t o = (size_t)n2 * K_ + k2;
        Thi[o] = h;
        Tlo[o] = __float2bfloat16(x - __bfloat162float(h));
    }
}

// ======================= common GEMM plumbing ===============================
#define BK      64
#define NCHUNK  (K_ / BK)          // 16
#define TILE_B  (128 * 128)        // 16 KB: 128 rows x 64 halfwords (128B/row)

// swizzled byte offset within one tile for (row, 16B-unit u in 0..7)
__device__ __forceinline__ uint32_t sw_off(int r, int u) {
    return (uint32_t)(r * 128 + ((u ^ (r & 7)) << 4));
}

// ======================= 3-product bf16 GEMM (input path) ===================
#define STAGE3_B (4 * TILE_B)            // 64 KB
#define GEMM3_SMEM (2 * STAGE3_B)        // 128 KB

__device__ __forceinline__ void load_stage3(const __nv_bfloat16* __restrict__ Ahi,
                                            const __nv_bfloat16* __restrict__ Alo,
                                            const __nv_bfloat16* __restrict__ Bhi,
                                            const __nv_bfloat16* __restrict__ Blo,
                                            int rowBase, int colBase, int k0,
                                            uint32_t stage, int tid) {
#pragma unroll
    for (int i = 0; i < 4; i++) {
        int e = tid + i * 256;
        int r = e >> 3, u = e & 7;
        uint32_t so = sw_off(r, u);
        size_t goA = (size_t)(rowBase + r) * K_ + k0 + u * 8;
        size_t goB = (size_t)(colBase + r) * K_ + k0 + u * 8;
        cp16(stage + 0 * TILE_B + so, Ahi + goA);
        cp16(stage + 1 * TILE_B + so, Alo + goA);
        cp16(stage + 2 * TILE_B + so, Bhi + goB);
        cp16(stage + 3 * TILE_B + so, Blo + goB);
    }
}

__global__ __launch_bounds__(256, 1)
void gemm_bf16s(const __nv_bfloat16* __restrict__ Ahi,
                const __nv_bfloat16* __restrict__ Alo,
                const __nv_bfloat16* __restrict__ Bhi,
                const __nv_bfloat16* __restrict__ Blo,
                const float* __restrict__ bias,
                float* __restrict__ C, int N)
{
    extern __shared__ char smem[];
    const uint32_t sbase = smem_u32(smem);
    const int tid  = threadIdx.x;
    const int wid  = tid >> 5;
    const int lane = tid & 31;
    const int warp_m = wid & 1;
    const int warp_n = wid >> 1;
    const int rowBase = blockIdx.x * 128;
    const int colBase = blockIdx.y * 128;

    float acc[4][4][4];
#pragma unroll
    for (int i = 0; i < 4; i++)
#pragma unroll
        for (int j = 0; j < 4; j++)
#pragma unroll
            for (int q = 0; q < 4; q++) acc[i][j][q] = 0.f;

    const int a_row = warp_m * 64 + (lane & 15);
    const int a_uo  = lane >> 4;
    const int b_row = warp_n * 32 + ((lane >> 4) << 3) + (lane & 7);
    const int b_uo  = (lane >> 3) & 1;

    uint32_t ahi[2][4][4], alo[2][4][4], bhi[2][2][4], blo[2][2][4];

    load_stage3(Ahi, Alo, Bhi, Blo, rowBase, colBase, 0, sbase, tid);
    CP_COMMIT();

    for (int k = 0; k < NCHUNK; k++) {
        __syncthreads();
        if (k + 1 < NCHUNK) {
            load_stage3(Ahi, Alo, Bhi, Blo, rowBase, colBase, (k + 1) * BK,
                        sbase + ((k + 1) & 1) * STAGE3_B, tid);
            CP_COMMIT();
            CP_WAIT(1);
        } else {
            CP_WAIT(0);
        }
        __syncthreads();

        const uint32_t st = sbase + (k & 1) * STAGE3_B;
#pragma unroll
        for (int i = 0; i < 4; i++) {
            uint32_t off = sw_off(a_row + i * 16, a_uo);
            ldsm4(ahi[0][i], st + off);
            ldsm4(alo[0][i], st + TILE_B + off);
        }
#pragma unroll
        for (int p = 0; p < 2; p++) {
            uint32_t off = sw_off(b_row + p * 16, b_uo);
            ldsm4(bhi[0][p], st + 2 * TILE_B + off);
            ldsm4(blo[0][p], st + 3 * TILE_B + off);
        }
#pragma unroll
        for (int s = 0; s < 4; s++) {
            const int cb = s & 1;
            if (s < 3) {
#pragma unroll
                for (int i = 0; i < 4; i++) {
                    uint32_t off = sw_off(a_row + i * 16, 2 * (s + 1) + a_uo);
                    ldsm4(ahi[cb ^ 1][i], st + off);
                    ldsm4(alo[cb ^ 1][i], st + TILE_B + off);
                }
#pragma unroll
                for (int p = 0; p < 2; p++) {
                    uint32_t off = sw_off(b_row + p * 16, 2 * (s + 1) + b_uo);
                    ldsm4(bhi[cb ^ 1][p], st + 2 * TILE_B + off);
                    ldsm4(blo[cb ^ 1][p], st + 3 * TILE_B + off);
                }
            }
#pragma unroll
            for (int i = 0; i < 4; i++) {
#pragma unroll
                for (int j = 0; j < 4; j++) {
                    const uint32_t* bh = &bhi[cb][j >> 1][(j & 1) * 2];
                    const uint32_t* bl = &blo[cb][j >> 1][(j & 1) * 2];
                    mma_bf16(acc[i][j], ahi[cb][i], bh);
                    mma_bf16(acc[i][j], ahi[cb][i], bl);
                    mma_bf16(acc[i][j], alo[cb][i], bh);
                }
            }
        }
    }

#pragma unroll
    for (int i = 0; i < 4; i++) {
        int row0 = rowBase + warp_m * 64 + i * 16 + (lane >> 2);
#pragma unroll
        for (int j = 0; j < 4; j++) {
            int col = colBase + warp_n * 32 + j * 8 + (lane & 3) * 2;
            float b0 = bias[col], b1 = bias[col + 1];
            float2 v0 = make_float2(acc[i][j][0] + b0, acc[i][j][1] + b1);
            float2 v1 = make_float2(acc[i][j][2] + b0, acc[i][j][3] + b1);
            *(float2*)(C + (size_t)row0 * N + col)       = v0;
            *(float2*)(C + (size_t)(row0 + 8) * N + col) = v1;
        }
    }
}

// ======================= 1-product fp16 GEMM (projection) ===================
// C = Ah @ Bh^T + bias. 2 CTAs/SM (4 warps/SMSP) to hide MMA dependency latency.
#define STAGE1_B (2 * TILE_B)            // 32 KB
#define GEMM1_SMEM (2 * STAGE1_B)        // 64 KB

__device__ __forceinline__ void load_stage1(const __half* __restrict__ Ah,
                                            const __half* __restrict__ Bh,
                                            int rowBase, int colBase, int k0,
                                            uint32_t stage, int tid) {
#pragma unroll
    for (int i = 0; i < 4; i++) {
        int e = tid + i * 256;
        int r = e >> 3, u = e & 7;
        uint32_t so = sw_off(r, u);
        cp16(stage + so,          Ah + (size_t)(rowBase + r) * K_ + k0 + u * 8);
        cp16(stage + TILE_B + so, Bh + (size_t)(colBase + r) * K_ + k0 + u * 8);
    }
}

__global__ __launch_bounds__(256, 2)
void gemm_f16_1(const __half* __restrict__ Ah,
                const __half* __restrict__ Bh,
                const float* __restrict__ bias,
                float* __restrict__ C, int N)
{
    extern __shared__ char smem[];
    const uint32_t sbase = smem_u32(smem);
    const int tid  = threadIdx.x;
    const int wid  = tid >> 5;
    const int lane = tid & 31;
    const int warp_m = wid & 1;
    const int warp_n = wid >> 1;
    const int rowBase = blockIdx.x * 128;   // m fastest -> B-tile reuse in L2
    const int colBase = blockIdx.y * 128;

    float acc[4][4][4];
#pragma unroll
    for (int i = 0; i < 4; i++)
#pragma unroll
        for (int j = 0; j < 4; j++)
#pragma unroll
            for (int q = 0; q < 4; q++) acc[i][j][q] = 0.f;

    const int a_row = warp_m * 64 + (lane & 15);
    const int a_uo  = lane >> 4;
    const int b_row = warp_n * 32 + ((lane >> 4) << 3) + (lane & 7);
    const int b_uo  = (lane >> 3) & 1;

    uint32_t ah[2][4][4], bh[2][2][4];

    load_stage1(Ah, Bh, rowBase, colBase, 0, sbase, tid);
    CP_COMMIT();

    for (int k = 0; k < NCHUNK; k++) {
        __syncthreads();
        if (k + 1 < NCHUNK) {
            load_stage1(Ah, Bh, rowBase, colBase, (k + 1) * BK,
                        sbase + ((k + 1) & 1) * STAGE1_B, tid);
            CP_COMMIT();
            CP_WAIT(1);
        } else {
            CP_WAIT(0);
        }
        __syncthreads();

        const uint32_t st = sbase + (k & 1) * STAGE1_B;
#pragma unroll
        for (int i = 0; i < 4; i++)
            ldsm4(ah[0][i], st + sw_off(a_row + i * 16, a_uo));
#pragma unroll
        for (int p = 0; p < 2; p++)
            ldsm4(bh[0][p], st + TILE_B + sw_off(b_row + p * 16, b_uo));
#pragma unroll
        for (int s = 0; s < 4; s++) {
            const int cb = s & 1;
            if (s < 3) {
#pragma unroll
                for (int i = 0; i < 4; i++)
                    ldsm4(ah[cb ^ 1][i],
                          st + sw_off(a_row + i * 16, 2 * (s + 1) + a_uo));
#pragma unroll
                for (int p = 0; p < 2; p++)
                    ldsm4(bh[cb ^ 1][p],
                          st + TILE_B + sw_off(b_row + p * 16, 2 * (s + 1) + b_uo));
            }
#pragma unroll
            for (int i = 0; i < 4; i++)
#pragma unroll
                for (int j = 0; j < 4; j++)
                    mma_f16(acc[i][j], ah[cb][i],
                            &bh[cb][j >> 1][(j & 1) * 2]);
        }
    }

#pragma unroll
    for (int i = 0; i < 4; i++) {
        int row0 = rowBase + warp_m * 64 + i * 16 + (lane >> 2);
#pragma unroll
        for (int j = 0; j < 4; j++) {
            int col = colBase + warp_n * 32 + j * 8 + (lane & 3) * 2;
            float b0 = bias[col], b1 = bias[col + 1];
            float2 v0 = make_float2(acc[i][j][0] + b0, acc[i][j][1] + b1);
            float2 v1 = make_float2(acc[i][j][2] + b0, acc[i][j][3] + b1);
            *(float2*)(C + (size_t)row0 * N + col)       = v0;
            *(float2*)(C + (size_t)(row0 + 8) * N + col) = v1;
        }
    }
}

// ======================= persistent fused LSTM + Wd transpose ===============
// CTAs 0..127: LSTM (warp w owns column j = cta*8+w; WhT slice in smem).
// CTAs 128..147: transpose Wd fp32 [1024 x 32000] -> g_WdT fp16 [32000 x 1024]
// in the shadow of the recurrence, then exit. Grid barrier counts 128 only.
__device__ __forceinline__ float sigmoidf_(float x) {
    return 1.f / (1.f + __expf(-x));
}

__global__ __launch_bounds__(256, 1)
void lstm_persist(const float* __restrict__ Wd) {
    extern __shared__ float sW[];       // lstm: [8 warps][4 gates][1024]
    const int tid  = threadIdx.x;
    const int cta  = blockIdx.x;

    if (cta >= LSTM_CTAS) {
        // ---- Wd transposer ----
        float* tile = sW;               // reuse dyn smem as 32x33 tile
        const int tx = tid & 31, ty = tid >> 5;     // 32 x 8
        const int NT = (V_ / 32) * (K_ / 32);       // 32000 tiles
        for (int tix = cta - LSTM_CTAS; tix < NT; tix += TRANS_CTAS) {
            int bx = tix % (V_ / 32);   // n tile
            int by = tix / (V_ / 32);   // k tile
            int n  = bx * 32 + tx;
            int k0 = by * 32;
#pragma unroll
            for (int r = ty; r < 32; r += 8)
                tile[r * 33 + tx] = Wd[(size_t)(k0 + r) * V_ + n];
            __syncthreads();
#pragma unroll
            for (int rr = ty; rr < 32; rr += 8) {
                int n2 = bx * 32 + rr;
                int k2 = k0 + tx;
                g_WdT[(size_t)n2 * K_ + k2] =
                    __float2half_rn(tile[tx * 33 + rr]);
            }
            __syncthreads();
        }
        return;
    }

    // ---- LSTM CTA ----
    const int wid  = tid >> 5;
    const int lane = tid & 31;
    const int j    = cta * 8 + wid;

    for (int i = tid; i < 8192; i += 256) {
        int w   = i >> 10;
        int rem = i & 1023;
        int g   = rem >> 8;
        int q   = rem & 255;
        float4 v = *(const float4*)(g_WhT +
                     ((size_t)g * F_ + (size_t)(cta * 8 + w)) * F_ + q * 4);
        *(float4*)(sW + ((w * 4 + g) * 1024) + q * 4) = v;
    }
    __syncthreads();

    const float* sw0 = sW + (wid * 4 + 0) * 1024;
    const float* sw1 = sW + (wid * 4 + 1) * 1024;
    const float* sw2 = sW + (wid * 4 + 2) * 1024;
    const float* sw3 = sW + (wid * 4 + 3) * 1024;

    float creg = 0.f;

    for (int t = 0; t < T_; t++) {
        const float* __restrict__ hin = g_h[t & 1];
        float* __restrict__ hout      = g_h[(t + 1) & 1];

        float xg0 = 0.f, xg1 = 0.f, xg2 = 0.f, xg3 = 0.f;
        if (lane < 8) {
            size_t row = ((size_t)lane * T_ + t) * G4;
            xg0 = g_xW[row + 0 * F_ + j];
            xg1 = g_xW[row + 1 * F_ + j];
            xg2 = g_xW[row + 2 * F_ + j];
            xg3 = g_xW[row + 3 * F_ + j];
        }

        // gate dot products with packed f32x2 FMA; acc index = g*8 + b
        uint64_t acc[32];
#pragma unroll
        for (int i = 0; i < 32; i++) acc[i] = 0ull;

#pragma unroll 2
        for (int p = 0; p < 8; p++) {
            int k = (p * 32 + lane) * 4;
            ulonglong2 w0 = *(const ulonglong2*)(sw0 + k);
            ulonglong2 w1 = *(const ulonglong2*)(sw1 + k);
            ulonglong2 w2 = *(const ulonglong2*)(sw2 + k);
            ulonglong2 w3 = *(const ulonglong2*)(sw3 + k);
#pragma unroll
            for (int b = 0; b < 8; b++) {
                ulonglong2 hv = *(const ulonglong2*)(hin + b * F_ + k);
                acc[0 * 8 + b] = fma2(w0.x, hv.x, acc[0 * 8 + b]);
                acc[0 * 8 + b] = fma2(w0.y, hv.y, acc[0 * 8 + b]);
                acc[1 * 8 + b] = fma2(w1.x, hv.x, acc[1 * 8 + b]);
                acc[1 * 8 + b] = fma2(w1.y, hv.y, acc[1 * 8 + b]);
                acc[2 * 8 + b] = fma2(w2.x, hv.x, acc[2 * 8 + b]);
                acc[2 * 8 + b] = fma2(w2.y, hv.y, acc[2 * 8 + b]);
                acc[3 * 8 + b] = fma2(w3.x, hv.x, acc[3 * 8 + b]);
                acc[3 * 8 + b] = fma2(w3.y, hv.y, acc[3 * 8 + b]);
            }
        }

        float v[32];
#pragma unroll
        for (int i = 0; i < 32; i++) v[i] = unpack_add(acc[i]);

        // merging-tree warp reduce: lane l ends with total of array l
#pragma unroll
        for (int m = 16; m; m >>= 1) {
#pragma unroll
            for (int i = 0; i < m; i++) {
                float send = (lane & m) ? v[i] : v[i + m];
                float recv = __shfl_xor_sync(0xffffffffu, send, m);
                float keep = (lane & m) ? v[i + m] : v[i];
                v[i] = keep + recv;
            }
        }
        float total = v[0];
        int bsel = lane & 7;
        float s0 = __shfl_sync(0xffffffffu, total, bsel);
        float s1 = __shfl_sync(0xffffffffu, total, 8 + bsel);
        float s2 = __shfl_sync(0xffffffffu, total, 16 + bsel);
        float s3 = __shfl_sync(0xffffffffu, total, 24 + bsel);

        if (lane < 8) {
            float zi = s0 + xg0;
            float zf = s1 + xg1;
            float zg = s2 + xg2;
            float zo = s3 + xg3;

            float cn = sigmoidf_(zf) * creg + sigmoidf_(zi) * tanhf(zg);
            float hn = sigmoidf_(zo) * tanhf(cn);
            creg = cn;

            hout[lane * F_ + j] = hn;
            g_Ah[((size_t)lane * T_ + t) * K_ + j] = __float2half_rn(hn);
        }

        // grid barrier: last arriver releases via clean flag word
        __threadfence();
        __syncthreads();
        if (tid == 0) {
            unsigned prev = atomicAdd(&g_bar, 1u);
            unsigned target = (unsigned)LSTM_CTAS * (unsigned)(t + 1);
            if (prev == target - 1u) {
                asm volatile("st.global.release.gpu.u32 [%0], %1;"
                             :: "l"(&g_rel), "r"((unsigned)(t + 1)) : "memory");
            } else {
                unsigned vv;
                do {
                    asm volatile("ld.global.acquire.gpu.u32 %0, [%1];"
                                 : "=r"(vv) : "l"(&g_rel));
                } while (vv < (unsigned)(t + 1));
            }
        }
        __syncthreads();
    }
}

// ======================= launch =============================================
extern "C" void kernel_launch(void* const* d_in, const int* in_sizes, int n_in,
                              void* d_out, int out_size) {
    const int*   tokens = (const int*)  d_in[0];
    const float* embed  = (const float*)d_in[1];
    const float* Wx     = (const float*)d_in[2];
    const float* Wh     = (const float*)d_in[3];
    const float* bias   = (const float*)d_in[4];
    const float* Wd     = (const float*)d_in[5];
    const float* bd     = (const float*)d_in[6];
    float* out = (float*)d_out;

    float *xW = nullptr;
    __nv_bfloat16 *ahi = nullptr, *alo = nullptr, *wxh = nullptr, *wxl = nullptr;
    __half *ah = nullptr, *wdt = nullptr;
    cudaGetSymbolAddress((void**)&xW,  g_xW);
    cudaGetSymbolAddress((void**)&ahi, g_Ahi);
    cudaGetSymbolAddress((void**)&alo, g_Alo);
    cudaGetSymbolAddress((void**)&wxh, g_WxT_hi);
    cudaGetSymbolAddress((void**)&wxl, g_WxT_lo);
    cudaGetSymbolAddress((void**)&ah,  g_Ah);
    cudaGetSymbolAddress((void**)&wdt, g_WdT);

    cudaFuncSetAttribute(gemm_bf16s,
                         cudaFuncAttributeMaxDynamicSharedMemorySize, GEMM3_SMEM);
    cudaFuncSetAttribute(gemm_f16_1,
                         cudaFuncAttributeMaxDynamicSharedMemorySize, GEMM1_SMEM);
    cudaFuncSetAttribute(gemm_f16_1,
                         cudaFuncAttributePreferredSharedMemoryCarveout, 100);
    cudaFuncSetAttribute(lstm_persist,
                         cudaFuncAttributeMaxDynamicSharedMemorySize, 131072);

    init_state<<<(B_ * F_ + 255) / 256, 256>>>();
    transpose_wh<<<dim3(G4 / 32, F_ / 32), dim3(32, 32)>>>(Wh);

    // ---- input path: x = embed[tokens]; xW = x @ Wx + b (bf16 3-product) ----
    split_rows<<<(M_ * K_ + 255) / 256, 256>>>(embed, tokens, ahi, alo);
    transpose_split<<<dim3(G4 / 32, K_ / 32), dim3(32, 8)>>>(Wx, wxh, wxl, G4);
    gemm_bf16s<<<dim3(M_ / 128, G4 / 128), 256, GEMM3_SMEM>>>(
        ahi, alo, wxh, wxl, bias, xW, G4);

    // ---- recurrence + Wd transpose in its shadow ----
    lstm_persist<<<LSTM_CTAS + TRANS_CTAS, 256, 131072>>>(Wd);

    // ---- projection: out = hs @ Wd + bd (fp16 single product, 2 CTAs/SM) ----
    gemm_f16_1<<<dim3(M_ / 128, V_ / 128), 256, GEMM1_SMEM>>>(
        ah, wdt, bd, out, V_);
}

// round 14
// speedup vs baseline: 1.0038x; 1.0038x over previous
#include <cuda_runtime.h>
#include <cuda_bf16.h>
#include <cuda_fp16.h>
#include <math.h>
#include <stdint.h>

#define B_  8
#define T_  512
#define F_  1024
#define G4  4096           // 4*F
#define V_  32000
#define M_  (B_*T_)        // 4096 rows
#define K_  1024
#define LSTM_CTAS 128
#define TRANS_CTAS 20      // extra CTAs in lstm_persist that transpose Wd

// ---------------- scratch (device globals; no allocation allowed) ----------
__device__ float g_xW[(size_t)M_ * G4];              // 64 MB : x@Wx + b
__device__ float g_WhT[(size_t)G4 * F_];             // 16 MB : Wh^T [4F][F]
__device__ float g_h[2][B_ * F_];                    // ping-pong hidden state
__device__ unsigned g_bar;                           // grid barrier counter
__device__ unsigned g_rel;                           // grid barrier release flag
// bf16 split operands (input GEMM: exact to 2^-16, feeds recurrence)
__device__ __nv_bfloat16 g_Ahi[(size_t)M_ * K_];     // 8 MB : embed rows hi
__device__ __nv_bfloat16 g_Alo[(size_t)M_ * K_];     // 8 MB : embed rows lo
__device__ __nv_bfloat16 g_WxT_hi[(size_t)G4 * K_];  // 8 MB  [4F][F]
__device__ __nv_bfloat16 g_WxT_lo[(size_t)G4 * K_];  // 8 MB
// fp16 operands (projection GEMM: single product, calibrated err ~3e-4)
__device__ __half g_Ah[(size_t)M_ * K_];             // 8 MB : hs fp16
__device__ __half g_WdT[(size_t)V_ * K_];            // 64 MB [V][F] fp16

// ======================= PTX helpers (sm_103-safe) ==========================
__device__ __forceinline__ uint32_t smem_u32(const void* p) {
    uint32_t a;
    asm("{ .reg .u64 t; cvta.to.shared.u64 t, %1; cvt.u32.u64 %0, t; }"
        : "=r"(a) : "l"(p));
    return a;
}
__device__ __forceinline__ void cp16(uint32_t s, const void* g) {
    asm volatile("cp.async.cg.shared.global [%0], [%1], 16;"
                 :: "r"(s), "l"(g) : "memory");
}
#define CP_COMMIT() asm volatile("cp.async.commit_group;" ::: "memory")
#define CP_WAIT(n)  asm volatile("cp.async.wait_group %0;" :: "n"(n) : "memory")

__device__ __forceinline__ void ldsm4(uint32_t* r, uint32_t addr) {
    asm volatile("ldmatrix.sync.aligned.m8n8.x4.shared.b16 {%0,%1,%2,%3}, [%4];"
                 : "=r"(r[0]), "=r"(r[1]), "=r"(r[2]), "=r"(r[3]) : "r"(addr));
}
__device__ __forceinline__ void mma_bf16(float* c, const uint32_t* a,
                                         const uint32_t* b) {
    asm volatile(
        "mma.sync.aligned.m16n8k16.row.col.f32.bf16.bf16.f32 "
        "{%0,%1,%2,%3}, {%4,%5,%6,%7}, {%8,%9}, {%0,%1,%2,%3};"
        : "+f"(c[0]), "+f"(c[1]), "+f"(c[2]), "+f"(c[3])
        : "r"(a[0]), "r"(a[1]), "r"(a[2]), "r"(a[3]), "r"(b[0]), "r"(b[1]));
}
__device__ __forceinline__ void mma_f16(float* c, const uint32_t* a,
                                        const uint32_t* b) {
    asm volatile(
        "mma.sync.aligned.m16n8k16.row.col.f32.f16.f16.f32 "
        "{%0,%1,%2,%3}, {%4,%5,%6,%7}, {%8,%9}, {%0,%1,%2,%3};"
        : "+f"(c[0]), "+f"(c[1]), "+f"(c[2]), "+f"(c[3])
        : "r"(a[0]), "r"(a[1]), "r"(a[2]), "r"(a[3]), "r"(b[0]), "r"(b[1]));
}
// packed fp32x2 FMA (sm_100+ family, not 'a'-gated)
__device__ __forceinline__ uint64_t fma2(uint64_t a, uint64_t b, uint64_t c) {
    uint64_t d;
    asm("fma.rn.f32x2 %0, %1, %2, %3;" : "=l"(d) : "l"(a), "l"(b), "l"(c));
    return d;
}
__device__ __forceinline__ float unpack_add(uint64_t a) {
    float lo, hi;
    asm("mov.b64 {%0,%1}, %2;" : "=f"(lo), "=f"(hi) : "l"(a));
    return lo + hi;
}

// ======================= prep kernels =======================================
__global__ void init_state() {
    int i = blockIdx.x * blockDim.x + threadIdx.x;
    if (i < B_ * F_) { g_h[0][i] = 0.f; g_h[1][i] = 0.f; }
    if (i == 0) { g_bar = 0u; g_rel = 0u; }
}

__global__ void transpose_wh(const float* __restrict__ Wh) {
    __shared__ float tile[32][33];
    int n = blockIdx.x * 32 + threadIdx.x;
    int k = blockIdx.y * 32 + threadIdx.y;
    tile[threadIdx.y][threadIdx.x] = Wh[(size_t)k * G4 + n];
    __syncthreads();
    int n2 = blockIdx.x * 32 + threadIdx.y;
    int k2 = blockIdx.y * 32 + threadIdx.x;
    g_WhT[(size_t)n2 * F_ + k2] = tile[threadIdx.x][threadIdx.y];
}

// embed[tokens] fp32 -> hi/lo bf16 rows
__global__ void split_rows(const float* __restrict__ src,
                           const int* __restrict__ tokens,
                           __nv_bfloat16* __restrict__ hi,
                           __nv_bfloat16* __restrict__ lo) {
    size_t idx = (size_t)blockIdx.x * blockDim.x + threadIdx.x;
    if (idx >= (size_t)M_ * K_) return;
    size_t row = idx >> 10, col = idx & 1023;
    float x = src[(size_t)tokens[row] * K_ + col];
    __nv_bfloat16 h = __float2bfloat16(x);
    hi[idx] = h;
    lo[idx] = __float2bfloat16(x - __bfloat162float(h));
}

// W fp32 [1024 x N] -> WT hi/lo bf16 [N x 1024]   (Wx path)
__global__ void transpose_split(const float* __restrict__ W,
                                __nv_bfloat16* __restrict__ Thi,
                                __nv_bfloat16* __restrict__ Tlo, int N) {
    __shared__ float tile[32][33];
    int n  = blockIdx.x * 32 + threadIdx.x;
    int k0 = blockIdx.y * 32;
#pragma unroll
    for (int r = threadIdx.y; r < 32; r += 8)
        tile[r][threadIdx.x] = W[(size_t)(k0 + r) * N + n];
    __syncthreads();
#pragma unroll
    for (int rr = threadIdx.y; rr < 32; rr += 8) {
        int n2 = blockIdx.x * 32 + rr;
        int k2 = k0 + threadIdx.x;
        float x = tile[threadIdx.x][rr];
        __nv_bfloat16 h = __float2bfloat16(x);
        size_t o = (size_t)n2 * K_ + k2;
        Thi[o] = h;
        Tlo[o] = __float2bfloat16(x - __bfloat162float(h));
    }
}

// ======================= common GEMM plumbing ===============================
#define BK      64
#define NCHUNK  (K_ / BK)          // 16
#define TILE_B  (128 * 128)        // 16 KB: 128 rows x 64 halfwords (128B/row)

// swizzled byte offset within one tile for (row, 16B-unit u in 0..7)
__device__ __forceinline__ uint32_t sw_off(int r, int u) {
    return (uint32_t)(r * 128 + ((u ^ (r & 7)) << 4));
}

// ======================= 3-product bf16 GEMM (input path) ===================
#define STAGE3_B (4 * TILE_B)            // 64 KB
#define GEMM3_SMEM (2 * STAGE3_B)        // 128 KB

__device__ __forceinline__ void load_stage3(const __nv_bfloat16* __restrict__ Ahi,
                                            const __nv_bfloat16* __restrict__ Alo,
                                            const __nv_bfloat16* __restrict__ Bhi,
                                            const __nv_bfloat16* __restrict__ Blo,
                                            int rowBase, int colBase, int k0,
                                            uint32_t stage, int tid) {
#pragma unroll
    for (int i = 0; i < 4; i++) {
        int e = tid + i * 256;
        int r = e >> 3, u = e & 7;
        uint32_t so = sw_off(r, u);
        size_t goA = (size_t)(rowBase + r) * K_ + k0 + u * 8;
        size_t goB = (size_t)(colBase + r) * K_ + k0 + u * 8;
        cp16(stage + 0 * TILE_B + so, Ahi + goA);
        cp16(stage + 1 * TILE_B + so, Alo + goA);
        cp16(stage + 2 * TILE_B + so, Bhi + goB);
        cp16(stage + 3 * TILE_B + so, Blo + goB);
    }
}

__global__ __launch_bounds__(256, 1)
void gemm_bf16s(const __nv_bfloat16* __restrict__ Ahi,
                const __nv_bfloat16* __restrict__ Alo,
                const __nv_bfloat16* __restrict__ Bhi,
                const __nv_bfloat16* __restrict__ Blo,
                const float* __restrict__ bias,
                float* __restrict__ C, int N)
{
    extern __shared__ char smem[];
    const uint32_t sbase = smem_u32(smem);
    const int tid  = threadIdx.x;
    const int wid  = tid >> 5;
    const int lane = tid & 31;
    const int warp_m = wid & 1;
    const int warp_n = wid >> 1;
    const int rowBase = blockIdx.x * 128;
    const int colBase = blockIdx.y * 128;

    float acc[4][4][4];
#pragma unroll
    for (int i = 0; i < 4; i++)
#pragma unroll
        for (int j = 0; j < 4; j++)
#pragma unroll
            for (int q = 0; q < 4; q++) acc[i][j][q] = 0.f;

    const int a_row = warp_m * 64 + (lane & 15);
    const int a_uo  = lane >> 4;
    const int b_row = warp_n * 32 + ((lane >> 4) << 3) + (lane & 7);
    const int b_uo  = (lane >> 3) & 1;

    uint32_t ahi[2][4][4], alo[2][4][4], bhi[2][2][4], blo[2][2][4];

    load_stage3(Ahi, Alo, Bhi, Blo, rowBase, colBase, 0, sbase, tid);
    CP_COMMIT();

    for (int k = 0; k < NCHUNK; k++) {
        __syncthreads();
        if (k + 1 < NCHUNK) {
            load_stage3(Ahi, Alo, Bhi, Blo, rowBase, colBase, (k + 1) * BK,
                        sbase + ((k + 1) & 1) * STAGE3_B, tid);
            CP_COMMIT();
            CP_WAIT(1);
        } else {
            CP_WAIT(0);
        }
        __syncthreads();

        const uint32_t st = sbase + (k & 1) * STAGE3_B;
#pragma unroll
        for (int i = 0; i < 4; i++) {
            uint32_t off = sw_off(a_row + i * 16, a_uo);
            ldsm4(ahi[0][i], st + off);
            ldsm4(alo[0][i], st + TILE_B + off);
        }
#pragma unroll
        for (int p = 0; p < 2; p++) {
            uint32_t off = sw_off(b_row + p * 16, b_uo);
            ldsm4(bhi[0][p], st + 2 * TILE_B + off);
            ldsm4(blo[0][p], st + 3 * TILE_B + off);
        }
#pragma unroll
        for (int s = 0; s < 4; s++) {
            const int cb = s & 1;
            if (s < 3) {
#pragma unroll
                for (int i = 0; i < 4; i++) {
                    uint32_t off = sw_off(a_row + i * 16, 2 * (s + 1) + a_uo);
                    ldsm4(ahi[cb ^ 1][i], st + off);
                    ldsm4(alo[cb ^ 1][i], st + TILE_B + off);
                }
#pragma unroll
                for (int p = 0; p < 2; p++) {
                    uint32_t off = sw_off(b_row + p * 16, 2 * (s + 1) + b_uo);
                    ldsm4(bhi[cb ^ 1][p], st + 2 * TILE_B + off);
                    ldsm4(blo[cb ^ 1][p], st + 3 * TILE_B + off);
                }
            }
#pragma unroll
            for (int i = 0; i < 4; i++) {
#pragma unroll
                for (int j = 0; j < 4; j++) {
                    const uint32_t* bh = &bhi[cb][j >> 1][(j & 1) * 2];
                    const uint32_t* bl = &blo[cb][j >> 1][(j & 1) * 2];
                    mma_bf16(acc[i][j], ahi[cb][i], bh);
                    mma_bf16(acc[i][j], ahi[cb][i], bl);
                    mma_bf16(acc[i][j], alo[cb][i], bh);
                }
            }
        }
    }

#pragma unroll
    for (int i = 0; i < 4; i++) {
        int row0 = rowBase + warp_m * 64 + i * 16 + (lane >> 2);
#pragma unroll
        for (int j = 0; j < 4; j++) {
            int col = colBase + warp_n * 32 + j * 8 + (lane & 3) * 2;
            float b0 = bias[col], b1 = bias[col + 1];
            float2 v0 = make_float2(acc[i][j][0] + b0, acc[i][j][1] + b1);
            float2 v1 = make_float2(acc[i][j][2] + b0, acc[i][j][3] + b1);
            *(float2*)(C + (size_t)row0 * N + col)       = v0;
            *(float2*)(C + (size_t)(row0 + 8) * N + col) = v1;
        }
    }
}

// ======================= 1-product fp16 GEMM (projection) ===================
// C = Ah @ Bh^T + bias. 2 CTAs/SM (4 warps/SMSP) to hide MMA dependency latency.
#define STAGE1_B (2 * TILE_B)            // 32 KB
#define GEMM1_SMEM (2 * STAGE1_B)        // 64 KB

__device__ __forceinline__ void load_stage1(const __half* __restrict__ Ah,
                                            const __half* __restrict__ Bh,
                                            int rowBase, int colBase, int k0,
                                            uint32_t stage, int tid) {
#pragma unroll
    for (int i = 0; i < 4; i++) {
        int e = tid + i * 256;
        int r = e >> 3, u = e & 7;
        uint32_t so = sw_off(r, u);
        cp16(stage + so,          Ah + (size_t)(rowBase + r) * K_ + k0 + u * 8);
        cp16(stage + TILE_B + so, Bh + (size_t)(colBase + r) * K_ + k0 + u * 8);
    }
}

__global__ __launch_bounds__(256, 2)
void gemm_f16_1(const __half* __restrict__ Ah,
                const __half* __restrict__ Bh,
                const float* __restrict__ bias,
                float* __restrict__ C, int N)
{
    extern __shared__ char smem[];
    const uint32_t sbase = smem_u32(smem);
    const int tid  = threadIdx.x;
    const int wid  = tid >> 5;
    const int lane = tid & 31;
    const int warp_m = wid & 1;
    const int warp_n = wid >> 1;
    const int rowBase = blockIdx.x * 128;   // m fastest -> B-tile reuse in L2
    const int colBase = blockIdx.y * 128;

    float acc[4][4][4];
#pragma unroll
    for (int i = 0; i < 4; i++)
#pragma unroll
        for (int j = 0; j < 4; j++)
#pragma unroll
            for (int q = 0; q < 4; q++) acc[i][j][q] = 0.f;

    const int a_row = warp_m * 64 + (lane & 15);
    const int a_uo  = lane >> 4;
    const int b_row = warp_n * 32 + ((lane >> 4) << 3) + (lane & 7);
    const int b_uo  = (lane >> 3) & 1;

    uint32_t ah[2][4][4], bh[2][2][4];

    load_stage1(Ah, Bh, rowBase, colBase, 0, sbase, tid);
    CP_COMMIT();

    for (int k = 0; k < NCHUNK; k++) {
        __syncthreads();
        if (k + 1 < NCHUNK) {
            load_stage1(Ah, Bh, rowBase, colBase, (k + 1) * BK,
                        sbase + ((k + 1) & 1) * STAGE1_B, tid);
            CP_COMMIT();
            CP_WAIT(1);
        } else {
            CP_WAIT(0);
        }
        __syncthreads();

        const uint32_t st = sbase + (k & 1) * STAGE1_B;
#pragma unroll
        for (int i = 0; i < 4; i++)
            ldsm4(ah[0][i], st + sw_off(a_row + i * 16, a_uo));
#pragma unroll
        for (int p = 0; p < 2; p++)
            ldsm4(bh[0][p], st + TILE_B + sw_off(b_row + p * 16, b_uo));
#pragma unroll
        for (int s = 0; s < 4; s++) {
            const int cb = s & 1;
            if (s < 3) {
#pragma unroll
                for (int i = 0; i < 4; i++)
                    ldsm4(ah[cb ^ 1][i],
                          st + sw_off(a_row + i * 16, 2 * (s + 1) + a_uo));
#pragma unroll
                for (int p = 0; p < 2; p++)
                    ldsm4(bh[cb ^ 1][p],
                          st + TILE_B + sw_off(b_row + p * 16, 2 * (s + 1) + b_uo));
            }
#pragma unroll
            for (int i = 0; i < 4; i++)
#pragma unroll
                for (int j = 0; j < 4; j++)
                    mma_f16(acc[i][j], ah[cb][i],
                            &bh[cb][j >> 1][(j & 1) * 2]);
        }
    }

#pragma unroll
    for (int i = 0; i < 4; i++) {
        int row0 = rowBase + warp_m * 64 + i * 16 + (lane >> 2);
#pragma unroll
        for (int j = 0; j < 4; j++) {
            int col = colBase + warp_n * 32 + j * 8 + (lane & 3) * 2;
            float b0 = bias[col], b1 = bias[col + 1];
            float2 v0 = make_float2(acc[i][j][0] + b0, acc[i][j][1] + b1);
            float2 v1 = make_float2(acc[i][j][2] + b0, acc[i][j][3] + b1);
            *(float2*)(C + (size_t)row0 * N + col)       = v0;
            *(float2*)(C + (size_t)(row0 + 8) * N + col) = v1;
        }
    }
}

// ======================= persistent fused LSTM + Wd transpose ===============
// CTAs 0..127: LSTM (warp w owns column j = cta*8+w; WhT slice in smem).
// CTAs 128..147: transpose Wd fp32 [1024 x 32000] -> g_WdT fp16 [32000 x 1024]
// in the shadow of the recurrence, then exit. Grid barrier counts 128 only.
__device__ __forceinline__ float sigmoidf_(float x) {
    return 1.f / (1.f + __expf(-x));
}

__global__ __launch_bounds__(256, 1)
void lstm_persist(const float* __restrict__ Wd) {
    extern __shared__ float sW[];       // lstm: [8 warps][4 gates][1024]
    const int tid  = threadIdx.x;
    const int cta  = blockIdx.x;

    if (cta >= LSTM_CTAS) {
        // ---- Wd transposer ----
        float* tile = sW;               // reuse dyn smem as 32x33 tile
        const int tx = tid & 31, ty = tid >> 5;     // 32 x 8
        const int NT = (V_ / 32) * (K_ / 32);       // 32000 tiles
        for (int tix = cta - LSTM_CTAS; tix < NT; tix += TRANS_CTAS) {
            int bx = tix % (V_ / 32);   // n tile
            int by = tix / (V_ / 32);   // k tile
            int n  = bx * 32 + tx;
            int k0 = by * 32;
#pragma unroll
            for (int r = ty; r < 32; r += 8)
                tile[r * 33 + tx] = Wd[(size_t)(k0 + r) * V_ + n];
            __syncthreads();
#pragma unroll
            for (int rr = ty; rr < 32; rr += 8) {
                int n2 = bx * 32 + rr;
                int k2 = k0 + tx;
                g_WdT[(size_t)n2 * K_ + k2] =
                    __float2half_rn(tile[tx * 33 + rr]);
            }
            __syncthreads();
        }
        return;
    }

    // ---- LSTM CTA ----
    const int wid  = tid >> 5;
    const int lane = tid & 31;
    const int j    = cta * 8 + wid;

    for (int i = tid; i < 8192; i += 256) {
        int w   = i >> 10;
        int rem = i & 1023;
        int g   = rem >> 8;
        int q   = rem & 255;
        float4 v = *(const float4*)(g_WhT +
                     ((size_t)g * F_ + (size_t)(cta * 8 + w)) * F_ + q * 4);
        *(float4*)(sW + ((w * 4 + g) * 1024) + q * 4) = v;
    }
    __syncthreads();

    const float* sw0 = sW + (wid * 4 + 0) * 1024;
    const float* sw1 = sW + (wid * 4 + 1) * 1024;
    const float* sw2 = sW + (wid * 4 + 2) * 1024;
    const float* sw3 = sW + (wid * 4 + 3) * 1024;

    float creg = 0.f;

    for (int t = 0; t < T_; t++) {
        const float* __restrict__ hin = g_h[t & 1];
        float* __restrict__ hout      = g_h[(t + 1) & 1];

        float xg0 = 0.f, xg1 = 0.f, xg2 = 0.f, xg3 = 0.f;
        if (lane < 8) {
            size_t row = ((size_t)lane * T_ + t) * G4;
            xg0 = g_xW[row + 0 * F_ + j];
            xg1 = g_xW[row + 1 * F_ + j];
            xg2 = g_xW[row + 2 * F_ + j];
            xg3 = g_xW[row + 3 * F_ + j];
        }

        // gate dot products with packed f32x2 FMA; acc index = g*8 + b
        uint64_t acc[32];
#pragma unroll
        for (int i = 0; i < 32; i++) acc[i] = 0ull;

#pragma unroll 2
        for (int p = 0; p < 8; p++) {
            int k = (p * 32 + lane) * 4;
            ulonglong2 w0 = *(const ulonglong2*)(sw0 + k);
            ulonglong2 w1 = *(const ulonglong2*)(sw1 + k);
            ulonglong2 w2 = *(const ulonglong2*)(sw2 + k);
            ulonglong2 w3 = *(const ulonglong2*)(sw3 + k);
#pragma unroll
            for (int b = 0; b < 8; b++) {
                ulonglong2 hv = *(const ulonglong2*)(hin + b * F_ + k);
                acc[0 * 8 + b] = fma2(w0.x, hv.x, acc[0 * 8 + b]);
                acc[0 * 8 + b] = fma2(w0.y, hv.y, acc[0 * 8 + b]);
                acc[1 * 8 + b] = fma2(w1.x, hv.x, acc[1 * 8 + b]);
                acc[1 * 8 + b] = fma2(w1.y, hv.y, acc[1 * 8 + b]);
                acc[2 * 8 + b] = fma2(w2.x, hv.x, acc[2 * 8 + b]);
                acc[2 * 8 + b] = fma2(w2.y, hv.y, acc[2 * 8 + b]);
                acc[3 * 8 + b] = fma2(w3.x, hv.x, acc[3 * 8 + b]);
                acc[3 * 8 + b] = fma2(w3.y, hv.y, acc[3 * 8 + b]);
            }
        }

        float v[32];
#pragma unroll
        for (int i = 0; i < 32; i++) v[i] = unpack_add(acc[i]);

        // merging-tree warp reduce: lane l ends with total of array l
#pragma unroll
        for (int m = 16; m; m >>= 1) {
#pragma unroll
            for (int i = 0; i < m; i++) {
                float send = (lane & m) ? v[i] : v[i + m];
                float recv = __shfl_xor_sync(0xffffffffu, send, m);
                float keep = (lane & m) ? v[i + m] : v[i];
                v[i] = keep + recv;
            }
        }
        float total = v[0];
        int bsel = lane & 7;
        float s0 = __shfl_sync(0xffffffffu, total, bsel);
        float s1 = __shfl_sync(0xffffffffu, total, 8 + bsel);
        float s2 = __shfl_sync(0xffffffffu, total, 16 + bsel);
        float s3 = __shfl_sync(0xffffffffu, total, 24 + bsel);

        if (lane < 8) {
            float zi = s0 + xg0;
            float zf = s1 + xg1;
            float zg = s2 + xg2;
            float zo = s3 + xg3;

            float cn = sigmoidf_(zf) * creg + sigmoidf_(zi) * tanhf(zg);
            float hn = sigmoidf_(zo) * tanhf(cn);
            creg = cn;

            hout[lane * F_ + j] = hn;
            g_Ah[((size_t)lane * T_ + t) * K_ + j] = __float2half_rn(hn);
        }

        // grid barrier: last arriver releases via clean flag word
        __threadfence();
        __syncthreads();
        if (tid == 0) {
            unsigned prev = atomicAdd(&g_bar, 1u);
            unsigned target = (unsigned)LSTM_CTAS * (unsigned)(t + 1);
            if (prev == target - 1u) {
                asm volatile("st.global.release.gpu.u32 [%0], %1;"
                             :: "l"(&g_rel), "r"((unsigned)(t + 1)) : "memory");
            } else {
                unsigned vv;
                do {
                    asm volatile("ld.global.acquire.gpu.u32 %0, [%1];"
                                 : "=r"(vv) : "l"(&g_rel));
                } while (vv < (unsigned)(t + 1));
            }
        }
        __syncthreads();
    }
}

// ======================= launch =============================================
extern "C" void kernel_launch(void* const* d_in, const int* in_sizes, int n_in,
                              void* d_out, int out_size) {
    const int*   tokens = (const int*)  d_in[0];
    const float* embed  = (const float*)d_in[1];
    const float* Wx     = (const float*)d_in[2];
    const float* Wh     = (const float*)d_in[3];
    const float* bias   = (const float*)d_in[4];
    const float* Wd     = (const float*)d_in[5];
    const float* bd     = (const float*)d_in[6];
    float* out = (float*)d_out;

    float *xW = nullptr;
    __nv_bfloat16 *ahi = nullptr, *alo = nullptr, *wxh = nullptr, *wxl = nullptr;
    __half *ah = nullptr, *wdt = nullptr;
    cudaGetSymbolAddress((void**)&xW,  g_xW);
    cudaGetSymbolAddress((void**)&ahi, g_Ahi);
    cudaGetSymbolAddress((void**)&alo, g_Alo);
    cudaGetSymbolAddress((void**)&wxh, g_WxT_hi);
    cudaGetSymbolAddress((void**)&wxl, g_WxT_lo);
    cudaGetSymbolAddress((void**)&ah,  g_Ah);
    cudaGetSymbolAddress((void**)&wdt, g_WdT);

    cudaFuncSetAttribute(gemm_bf16s,
                         cudaFuncAttributeMaxDynamicSharedMemorySize, GEMM3_SMEM);
    cudaFuncSetAttribute(gemm_f16_1,
                         cudaFuncAttributeMaxDynamicSharedMemorySize, GEMM1_SMEM);
    cudaFuncSetAttribute(gemm_f16_1,
                         cudaFuncAttributePreferredSharedMemoryCarveout, 100);
    cudaFuncSetAttribute(lstm_persist,
                         cudaFuncAttributeMaxDynamicSharedMemorySize, 131072);

    init_state<<<(B_ * F_ + 255) / 256, 256>>>();
    transpose_wh<<<dim3(G4 / 32, F_ / 32), dim3(32, 32)>>>(Wh);

    // ---- input path: x = embed[tokens]; xW = x @ Wx + b (bf16 3-product) ----
    split_rows<<<(M_ * K_ + 255) / 256, 256>>>(embed, tokens, ahi, alo);
    transpose_split<<<dim3(G4 / 32, K_ / 32), dim3(32, 8)>>>(Wx, wxh, wxl, G4);
    gemm_bf16s<<<dim3(M_ / 128, G4 / 128), 256, GEMM3_SMEM>>>(
        ahi, alo, wxh, wxl, bias, xW, G4);

    // ---- recurrence + Wd transpose in its shadow ----
    lstm_persist<<<LSTM_CTAS + TRANS_CTAS, 256, 131072>>>(Wd);

    // ---- projection: out = hs @ Wd + bd (fp16 single product, 2 CTAs/SM) ----
    gemm_f16_1<<<dim3(M_ / 128, V_ / 128), 256, GEMM1_SMEM>>>(
        ah, wdt, bd, out, V_);
}